// round 2
// baseline (speedup 1.0000x reference)
#include <cuda_runtime.h>
#include <cstdint>
#include <cstddef>

#define NTHR 256
#define TB 8
#define PITCH 132

// smem layout (floats)
// Ws : 131*132 = 17292   staged weight tile (pitch 132, conflict-free both directions)
// Xs : 8*132   = 1056    per-example input vector (131 used)
// Hs : 4*8*128 = 4096    forward activations h1..h4 (masks for backward)
// Ua : 8*128   = 1024    backward vector ping
// Ub : 8*128   = 1024    backward vector pong
// small: sS,cS,xsS,valS (8 ea) + idxS (8 int)
#define WS_OFF   0
#define XS_OFF   17292
#define HS_OFF   18348
#define UA_OFF   22444
#define UB_OFF   23468
#define SMALL_OFF 24492
#define SMEM_FLOATS (SMALL_OFF + 40)
#define SMEM_BYTES (SMEM_FLOATS * 4)

__device__ __forceinline__ void stage_w(float* Ws, const float* __restrict__ g, int rows, int tid) {
    for (int i4 = tid; i4 < rows * 32; i4 += NTHR) {
        int r = i4 >> 5, c4 = (i4 & 31) << 2;
        *(float4*)(Ws + r * PITCH + c4) = *(const float4*)(g + r * 128 + c4);
    }
}

// zero one example's d2f row block (16384 floats), skipping the first float4
// (written later with {h00,0,0,0} by the output phase)
#define ZCHUNK(e_) do {                                                         \
    float4 z4 = make_float4(0.f, 0.f, 0.f, 0.f);                                \
    float4* dst_ = (float4*)(o_d2f + (size_t)(b0 + (e_)) * 16384);              \
    for (int i_ = 1 + tid; i_ < 4096; i_ += NTHR) dst_[i_] = z4;                \
  } while (0)

#define BACKSTEP(UIN, UOUT, LVL) do {                                           \
    float acc_[4] = {0.f, 0.f, 0.f, 0.f};                                       \
    _Pragma("unroll 8")                                                         \
    for (int k = 0; k < 128; k += 4) {                                          \
        float4 wv = *(const float4*)(Ws + t * PITCH + k);                       \
        _Pragma("unroll")                                                       \
        for (int e = 0; e < 4; e++) {                                           \
            float4 uv = *(const float4*)((UIN) + (bbase + e) * 128 + k);        \
            acc_[e] = fmaf(wv.x, uv.x, acc_[e]);                                \
            acc_[e] = fmaf(wv.y, uv.y, acc_[e]);                                \
            acc_[e] = fmaf(wv.z, uv.z, acc_[e]);                                \
            acc_[e] = fmaf(wv.w, uv.w, acc_[e]);                                \
        }                                                                       \
    }                                                                           \
    _Pragma("unroll")                                                           \
    for (int e = 0; e < 4; e++) {                                               \
        float h = Hs[(LVL) * 1024 + (bbase + e) * 128 + t];                     \
        (UOUT)[(bbase + e) * 128 + t] = (h > 0.f) ? acc_[e] : 0.f;              \
    }                                                                           \
  } while (0)

__global__ void __launch_bounds__(NTHR)
fused_kernel(const float* __restrict__ centers,
             const float* __restrict__ eps,
             const float* __restrict__ dk,
             const float* __restrict__ Wi,
             const float* __restrict__ Wh,
             const float* __restrict__ bh,
             const float* __restrict__ bf,
             const void* __restrict__ pA2048, const void* __restrict__ pB2048,
             const float* __restrict__ pA128, const float* __restrict__ pB128,
             float* __restrict__ o_res, float* __restrict__ o_fmean,
             float* __restrict__ o_flog, float* __restrict__ o_coeffs,
             float* __restrict__ o_d1c, float* __restrict__ o_d2c,
             float* __restrict__ o_d1o, float* __restrict__ o_d2o,
             float* __restrict__ o_d1f, float* __restrict__ o_d2f)
{
    extern __shared__ float sm[];
    float* Ws = sm + WS_OFF;
    float* Xs = sm + XS_OFF;
    float* Hs = sm + HS_OFF;
    float* Ua = sm + UA_OFF;
    float* Ub = sm + UB_OFF;
    float* sS   = sm + SMALL_OFF;
    float* cS   = sS + TB;
    float* xsS  = cS + TB;
    float* valS = xsS + TB;
    int*   idxS = (int*)(valS + TB);

    const int tid = threadIdx.x;
    const int half = tid >> 7;
    const int t = tid & 127;
    const int b0 = blockIdx.x * TB;
    const int bbase = half * 4;

    // --- resolve ambiguous inputs (same size, different role) ---
    // indecies (int32, values 0..999) vs xs (float32 ~N(0,1)): int bit patterns
    // of normal floats are never all < 1000.
    const unsigned* ua_ = (const unsigned*)pA2048;
    bool a_idx = true;
#pragma unroll
    for (int i = 0; i < 8; i++) a_idx &= (ua_[i] < 1000u);
    const int*   idxp = (const int*)(a_idx ? pA2048 : pB2048);
    const float* xsp  = (const float*)(a_idx ? pB2048 : pA2048);
    // bi (all zeros) vs Wf (random normal / sqrt(128)): exact-zero check.
    bool a_bi = true;
#pragma unroll
    for (int i = 0; i < 8; i++) a_bi &= (pA128[i] == 0.0f);
    const float* bi = a_bi ? pA128 : pB128;
    const float* Wf = a_bi ? pB128 : pA128;

    // --- phase 0a: per-example scalars ---
    if (tid < TB) {
        int gb = b0 + tid;
        idxS[tid] = idxp[gb];
        cS[tid]   = centers[gb * 4];
        Xs[tid * PITCH + 1] = centers[gb * 4 + 1];
        Xs[tid * PITCH + 2] = centers[gb * 4 + 2];
        Xs[tid * PITCH + 3] = centers[gb * 4 + 3];
        xsS[tid]  = xsp[gb];
    }
    __syncthreads();

    // --- phase 0b: gather feat, write fmean/flog, build X; stage Wi ---
#pragma unroll
    for (int ii = 0; ii < 4; ii++) {
        int e2 = tid + NTHR * ii;
        int b = e2 >> 7;
        int k = e2 & 127;
        int gb = b0 + b;
        int id = idxS[b];
        float m  = dk[id * 256 + k];
        float ls = dk[id * 256 + 128 + k];
        float ep = eps[id * 128 + k];
        float ft = fmaf(expf(0.5f * ls), ep, m);
        o_fmean[(size_t)gb * 128 + k] = m;
        o_flog[(size_t)gb * 128 + k]  = ls;
        if (k == 0) {
            float s = 1e-10f + expf(-ft);
            sS[b] = s;
            Xs[b * PITCH] = cS[b] * s;
        } else {
            Xs[b * PITCH + 3 + k] = ft;
        }
    }
    stage_w(Ws, Wi, 131, tid);
    __syncthreads();

    ZCHUNK(0);

    // --- L1 forward: h1 = relu(x @ Wi + bi) ---
    {
        float acc[4];
        float bv = bi[t];
#pragma unroll
        for (int e = 0; e < 4; e++) acc[e] = bv;
#pragma unroll 8
        for (int k = 0; k < 128; k += 4) {
            float w0 = Ws[(k    ) * PITCH + t];
            float w1 = Ws[(k + 1) * PITCH + t];
            float w2 = Ws[(k + 2) * PITCH + t];
            float w3 = Ws[(k + 3) * PITCH + t];
#pragma unroll
            for (int e = 0; e < 4; e++) {
                float4 hv = *(const float4*)(Xs + (bbase + e) * PITCH + k);
                acc[e] = fmaf(hv.x, w0, acc[e]);
                acc[e] = fmaf(hv.y, w1, acc[e]);
                acc[e] = fmaf(hv.z, w2, acc[e]);
                acc[e] = fmaf(hv.w, w3, acc[e]);
            }
        }
#pragma unroll
        for (int k = 128; k < 131; k++) {
            float w = Ws[k * PITCH + t];
#pragma unroll
            for (int e = 0; e < 4; e++)
                acc[e] = fmaf(Xs[(bbase + e) * PITCH + k], w, acc[e]);
        }
#pragma unroll
        for (int e = 0; e < 4; e++)
            Hs[(bbase + e) * 128 + t] = fmaxf(acc[e], 0.f);
    }
    __syncthreads();
    ZCHUNK(1);

    // --- hidden layers 2..4 ---
    for (int l = 0; l < 3; l++) {
        stage_w(Ws, Wh + l * 16384, 128, tid);
        __syncthreads();
        float acc[4];
        float bv = bh[l * 128 + t];
#pragma unroll
        for (int e = 0; e < 4; e++) acc[e] = bv;
        const float* hin = Hs + l * 1024;
#pragma unroll 8
        for (int k = 0; k < 128; k += 4) {
            float w0 = Ws[(k    ) * PITCH + t];
            float w1 = Ws[(k + 1) * PITCH + t];
            float w2 = Ws[(k + 2) * PITCH + t];
            float w3 = Ws[(k + 3) * PITCH + t];
#pragma unroll
            for (int e = 0; e < 4; e++) {
                float4 hv = *(const float4*)(hin + (bbase + e) * 128 + k);
                acc[e] = fmaf(hv.x, w0, acc[e]);
                acc[e] = fmaf(hv.y, w1, acc[e]);
                acc[e] = fmaf(hv.z, w2, acc[e]);
                acc[e] = fmaf(hv.w, w3, acc[e]);
            }
        }
#pragma unroll
        for (int e = 0; e < 4; e++)
            Hs[(l + 1) * 1024 + (bbase + e) * 128 + t] = fmaxf(acc[e], 0.f);
        __syncthreads();
        ZCHUNK(2 + l);
    }

    // --- val = h4 @ Wf + bf (warp-per-example) and backward init u4 = Wf .* m4 ---
    {
        int wrp = tid >> 5, lane = tid & 31;
        const float* h4 = Hs + 3 * 1024 + wrp * 128;
        float4 hv = *(const float4*)(h4 + lane * 4);
        float4 wv = *(const float4*)(Wf + lane * 4);
        float p = hv.x * wv.x + hv.y * wv.y + hv.z * wv.z + hv.w * wv.w;
#pragma unroll
        for (int o = 16; o > 0; o >>= 1) p += __shfl_down_sync(0xffffffffu, p, o);
        if (lane == 0) valS[wrp] = p + bf[0];

        float wf_t = Wf[t];
#pragma unroll
        for (int e = 0; e < 4; e++) {
            float h = Hs[3 * 1024 + (bbase + e) * 128 + t];
            Ua[(bbase + e) * 128 + t] = (h > 0.f) ? wf_t : 0.f;
        }
    }
    __syncthreads();
    ZCHUNK(5);

    // --- backward: Ws still holds Wh[2] ---
    BACKSTEP(Ua, Ub, 2);
    __syncthreads();
    stage_w(Ws, Wh + 1 * 16384, 128, tid);
    __syncthreads();
    BACKSTEP(Ub, Ua, 1);
    __syncthreads();
    ZCHUNK(6);
    stage_w(Ws, Wh + 0 * 16384, 128, tid);
    __syncthreads();
    BACKSTEP(Ua, Ub, 0);
    __syncthreads();
    ZCHUNK(7);
    stage_w(Ws, Wi, 131, tid);
    __syncthreads();

    // --- g = Wi @ u1 and all remaining outputs ---
    {
        float g[4] = {0.f, 0.f, 0.f, 0.f};
#pragma unroll 8
        for (int k = 0; k < 128; k += 4) {
            float4 wv = *(const float4*)(Ws + t * PITCH + k);
#pragma unroll
            for (int e = 0; e < 4; e++) {
                float4 uv = *(const float4*)(Ub + (bbase + e) * 128 + k);
                g[e] = fmaf(wv.x, uv.x, g[e]);
                g[e] = fmaf(wv.y, uv.y, g[e]);
                g[e] = fmaf(wv.z, uv.z, g[e]);
                g[e] = fmaf(wv.w, uv.w, g[e]);
            }
        }
        if (t >= 4) {
#pragma unroll
            for (int e = 0; e < 4; e++) {
                int gb = b0 + bbase + e;
                o_d1f[(size_t)gb * 128 + (t - 3)] = g[e];
            }
        } else if (t == 0) {
#pragma unroll
            for (int e = 0; e < 4; e++) {
                int bloc = bbase + e;
                int gb = b0 + bloc;
                float s = sS[bloc], c = cS[bloc], val = valS[bloc];
                float g0 = g[e];
                float d1c = g0 * s;
                float h00 = g0 * c * (s - 1e-10f);   // g0 * c * exp(-ft0)
                o_d1c[gb] = d1c;
                o_d2c[gb] = 0.f;
                o_coeffs[gb] = val;
                o_res[gb] = fmaf(d1c, xsS[bloc] - c, val);
                o_d1f[(size_t)gb * 128] = -h00;
                *(float4*)(o_d2f + (size_t)gb * 16384) = make_float4(h00, 0.f, 0.f, 0.f);
            }
        } else {  // t = 1..3
#pragma unroll
            for (int e = 0; e < 4; e++) {
                int gb = b0 + bbase + e;
                o_d1o[(size_t)gb * 3 + (t - 1)] = g[e];
            }
        }
        // extra Wi rows 128..130 -> d1f[125..127]
        if (t < 3) {
            int r = 128 + t;
            float ge[4] = {0.f, 0.f, 0.f, 0.f};
#pragma unroll 8
            for (int k = 0; k < 128; k += 4) {
                float4 wv = *(const float4*)(Ws + r * PITCH + k);
#pragma unroll
                for (int e = 0; e < 4; e++) {
                    float4 uv = *(const float4*)(Ub + (bbase + e) * 128 + k);
                    ge[e] = fmaf(wv.x, uv.x, ge[e]);
                    ge[e] = fmaf(wv.y, uv.y, ge[e]);
                    ge[e] = fmaf(wv.z, uv.z, ge[e]);
                    ge[e] = fmaf(wv.w, uv.w, ge[e]);
                }
            }
#pragma unroll
            for (int e = 0; e < 4; e++) {
                int gb = b0 + bbase + e;
                o_d1f[(size_t)gb * 128 + 125 + t] = ge[e];
            }
        }
        // d2o zeros (8 examples x 9 entries)
        if (tid < 72) {
            int b = tid / 9, k9 = tid % 9;
            o_d2o[(size_t)(b0 + b) * 9 + k9] = 0.f;
        }
    }
}

extern "C" void kernel_launch(void* const* d_in, const int* in_sizes, int n_in,
                              void* d_out, int out_size)
{
    (void)out_size;
    const float *centers = 0, *eps = 0, *dk = 0, *Wi = 0, *Wh = 0, *bh = 0, *bf = 0;
    const void* p2048[2] = {0, 0};
    const float* p128[2] = {0, 0};
    int n2 = 0, n1 = 0;
    for (int i = 0; i < n_in; i++) {
        switch (in_sizes[i]) {
            case 8192:   centers = (const float*)d_in[i]; break;  // (2048,4)
            case 128000: eps     = (const float*)d_in[i]; break;  // (1000,128)
            case 256000: dk      = (const float*)d_in[i]; break;  // (1000,256)
            case 16768:  Wi      = (const float*)d_in[i]; break;  // (131,128)
            case 49152:  Wh      = (const float*)d_in[i]; break;  // (3,128,128)
            case 384:    bh      = (const float*)d_in[i]; break;  // (3,128)
            case 1:      bf      = (const float*)d_in[i]; break;  // (1,)
            case 2048:   if (n2 < 2) p2048[n2++] = d_in[i]; break; // indecies / xs
            case 128:    if (n1 < 2) p128[n1++] = (const float*)d_in[i]; break; // bi / Wf
            default: break;
        }
    }
    const int B = 2048;
    float* out = (float*)d_out;
    float* o_res    = out;
    float* o_fmean  = out + B;
    float* o_flog   = o_fmean + (size_t)B * 128;
    float* o_coeffs = o_flog + (size_t)B * 128;
    float* o_d1c    = o_coeffs + B;
    float* o_d2c    = o_d1c + B;
    float* o_d1o    = o_d2c + B;
    float* o_d2o    = o_d1o + (size_t)B * 3;
    float* o_d1f    = o_d2o + (size_t)B * 9;
    float* o_d2f    = o_d1f + (size_t)B * 128;

    cudaFuncSetAttribute(fused_kernel, cudaFuncAttributeMaxDynamicSharedMemorySize, SMEM_BYTES);
    fused_kernel<<<B / TB, NTHR, SMEM_BYTES>>>(
        centers, eps, dk, Wi, Wh, bh, bf,
        p2048[0], p2048[1], p128[0], p128[1],
        o_res, o_fmean, o_flog, o_coeffs, o_d1c, o_d2c, o_d1o, o_d2o, o_d1f, o_d2f);
}